// round 12
// baseline (speedup 1.0000x reference)
#include <cuda_runtime.h>
#include <cuda_bf16.h>
#include <math.h>
#include <stdint.h>

#define BB 16
#define CC 128
#define HH 128
#define WW 128
#define NP (HH*WW)          // 16384 spatial

#define LDT 136             // padded smem row stride (bf16 elems) — conflict-free ldmatrix
#define TILE_B (128*LDT*2)  // 34816 bytes per 128x128 bf16 tile

// ---------------- scratch (device globals; no allocation allowed) ----------------
__device__ float g_t [3ull*BB*CC*NP];            // conv1x1 outputs fp32 (dwconv input)
__device__ float g_v [(size_t)BB*CC*NP];         // v after dwconv, fp32 [b][c][n]
__device__ __nv_bfloat16 g_xTh[(size_t)BB*NP*CC];// x transposed [b][n][c], hi
__device__ __nv_bfloat16 g_xTl[(size_t)BB*NP*CC];// lo
__device__ __nv_bfloat16 g_vTh[(size_t)BB*NP*CC];// v transposed, hi
__device__ __nv_bfloat16 g_vTl[(size_t)BB*NP*CC];
__device__ __nv_bfloat16 g_qh[(size_t)BB*CC*NP]; // q after dwconv [b][c][n], hi
__device__ __nv_bfloat16 g_ql[(size_t)BB*CC*NP];
__device__ __nv_bfloat16 g_kh[(size_t)BB*CC*NP];
__device__ __nv_bfloat16 g_kl[(size_t)BB*CC*NP];
__device__ __nv_bfloat16 g_wh[3ull*CC*CC];       // qw/kw/vw pre-split hi
__device__ __nv_bfloat16 g_wl[3ull*CC*CC];       // lo
__device__ __nv_bfloat16 g_Mh[(size_t)BB*CC*CC]; // M pre-split hi
__device__ __nv_bfloat16 g_Ml[(size_t)BB*CC*CC];
__device__ float g_ss[2*BB*CC];
__device__ float g_G [BB*CC*CC];
__device__ float g_A [BB*CC*CC];
__device__ float g_M [BB*CC*CC];

// ================= helpers =================
__device__ __forceinline__ uint32_t smem_u32(const void* p) {
    uint32_t a;
    asm("{ .reg .u64 t; cvta.to.shared.u64 t, %1; cvt.u32.u64 %0, t; }" : "=r"(a) : "l"(p));
    return a;
}

__device__ __forceinline__ void ldmx4(uint32_t addr, uint32_t* r) {
    asm volatile("ldmatrix.sync.aligned.m8n8.x4.shared.b16 {%0,%1,%2,%3}, [%4];"
        : "=r"(r[0]), "=r"(r[1]), "=r"(r[2]), "=r"(r[3]) : "r"(addr));
}

__device__ __forceinline__ void mma16816(float* d, const uint32_t* a, const uint32_t* b) {
    asm volatile("mma.sync.aligned.m16n8k16.row.col.f32.bf16.bf16.f32 "
        "{%0,%1,%2,%3}, {%4,%5,%6,%7}, {%8,%9}, {%0,%1,%2,%3};"
        : "+f"(d[0]), "+f"(d[1]), "+f"(d[2]), "+f"(d[3])
        : "r"(a[0]), "r"(a[1]), "r"(a[2]), "r"(a[3]), "r"(b[0]), "r"(b[1]));
}

__device__ __forceinline__ void packsplit(float x, float y, unsigned& h, unsigned& l) {
    __nv_bfloat16 hx = __float2bfloat16(x), hy = __float2bfloat16(y);
    __nv_bfloat16 lx = __float2bfloat16(x - __bfloat162float(hx));
    __nv_bfloat16 ly = __float2bfloat16(y - __bfloat162float(hy));
    h = (unsigned)__bfloat16_as_ushort(hx) | ((unsigned)__bfloat16_as_ushort(hy) << 16);
    l = (unsigned)__bfloat16_as_ushort(lx) | ((unsigned)__bfloat16_as_ushort(ly) << 16);
}

// copy a 128x128 bf16 tile into padded smem — 512-thread variant.
__device__ __forceinline__ void fill_tile512(const __nv_bfloat16* __restrict__ src,
                                             size_t stride, __nv_bfloat16* __restrict__ dst) {
    int t = threadIdx.x;
    int row = t >> 2, q = t & 3;
    const uint4* s = (const uint4*)(src + (size_t)row * stride) + q * 4;
    uint4* d = (uint4*)(dst + row * LDT) + q * 4;
#pragma unroll
    for (int i = 0; i < 4; i++) d[i] = s[i];
}

// ---- 16-warp 128x128x128 compensated bf16 MMA: acc += Ah.Bh^T + Al.Bh^T + Ah.Bl^T ----
// warp w: wm=w&3 (32-row slice), wn=w>>2 (32-col slice). acc[2][4][4].
__device__ __forceinline__ void mma_compute16(uint32_t sAh, uint32_t sAl,
                                              uint32_t sBh, uint32_t sBl,
                                              float acc[2][4][4]) {
    int w = threadIdx.x >> 5, lane = threadIdx.x & 31;
    int wm = w & 3, wn = w >> 2;

    int arow = lane & 15;
    int acol = (lane >> 4) * 8;
    uint32_t aoff[2];
#pragma unroll
    for (int mt = 0; mt < 2; mt++)
        aoff[mt] = ((wm * 32 + mt * 16 + arow) * LDT + acol) * 2;

    int brow = ((lane >> 4) & 1) * 8 + (lane & 7);
    int bcol = ((lane >> 3) & 1) * 8;
    uint32_t boff[2];
#pragma unroll
    for (int np = 0; np < 2; np++)
        boff[np] = ((wn * 32 + np * 16 + brow) * LDT + bcol) * 2;

#pragma unroll
    for (int ks = 0; ks < 8; ks++) {
        uint32_t kb = ks * 32;
        uint32_t ah[2][4], al[2][4], bb[2][4];
#pragma unroll
        for (int mt = 0; mt < 2; mt++) ldmx4(sAh + aoff[mt] + kb, ah[mt]);
#pragma unroll
        for (int np = 0; np < 2; np++) ldmx4(sBh + boff[np] + kb, bb[np]);
#pragma unroll
        for (int mt = 0; mt < 2; mt++)
#pragma unroll
            for (int nt = 0; nt < 4; nt++)
                mma16816(acc[mt][nt], ah[mt], &bb[nt >> 1][(nt & 1) * 2]);
#pragma unroll
        for (int mt = 0; mt < 2; mt++) ldmx4(sAl + aoff[mt] + kb, al[mt]);
#pragma unroll
        for (int mt = 0; mt < 2; mt++)
#pragma unroll
            for (int nt = 0; nt < 4; nt++)
                mma16816(acc[mt][nt], al[mt], &bb[nt >> 1][(nt & 1) * 2]);
#pragma unroll
        for (int np = 0; np < 2; np++) ldmx4(sBl + boff[np] + kb, bb[np]);
#pragma unroll
        for (int mt = 0; mt < 2; mt++)
#pragma unroll
            for (int nt = 0; nt < 4; nt++)
                mma16816(acc[mt][nt], ah[mt], &bb[nt >> 1][(nt & 1) * 2]);
    }
}

// ---------------- zero accumulators ----------------
__global__ void k_zero() {
    int i = blockIdx.x * blockDim.x + threadIdx.x;
    if (i < BB*CC*CC) g_G[i] = 0.0f;
    if (i < 2*BB*CC)  g_ss[i] = 0.0f;
}

// ---------------- pre-split weights to bf16 hi/lo ----------------
__global__ void __launch_bounds__(256) k_wsplit(const float* __restrict__ qw,
                                                const float* __restrict__ kw,
                                                const float* __restrict__ vw)
{
    int j = blockIdx.x;
    const float* W = (j == 0) ? qw : (j == 1) ? kw : vw;
    __nv_bfloat16* oh = g_wh + (size_t)j * CC * CC;
    __nv_bfloat16* ol = g_wl + (size_t)j * CC * CC;
    int t = threadIdx.x;
#pragma unroll
    for (int i = 0; i < 16; i++) {
        int l = t + i * 256;
        float4 a = ((const float4*)W)[l];
        unsigned h0, l0, h1, l1;
        packsplit(a.x, a.y, h0, l0);
        packsplit(a.z, a.w, h1, l1);
        ((uint2*)oh)[l] = make_uint2(h0, h1);
        ((uint2*)ol)[l] = make_uint2(l0, l1);
    }
}
__global__ void __launch_bounds__(256) k_Msplit()
{
    int b = blockIdx.x;
    const float* W = g_M + (size_t)b * CC * CC;
    __nv_bfloat16* oh = g_Mh + (size_t)b * CC * CC;
    __nv_bfloat16* ol = g_Ml + (size_t)b * CC * CC;
    int t = threadIdx.x;
#pragma unroll
    for (int i = 0; i < 16; i++) {
        int l = t + i * 256;
        float4 a = ((const float4*)W)[l];
        unsigned h0, l0, h1, l1;
        packsplit(a.x, a.y, h0, l0);
        packsplit(a.z, a.w, h1, l1);
        ((uint2*)oh)[l] = make_uint2(h0, h1);
        ((uint2*)ol)[l] = make_uint2(l0, l1);
    }
}

// ---------------- transpose + bf16 split: [b][c][n] fp32 -> [b][n][c] hi/lo ----------------
__device__ __forceinline__ void tsplit_body(const float* __restrict__ in,
                                            __nv_bfloat16* __restrict__ oh,
                                            __nv_bfloat16* __restrict__ ol) {
    __shared__ float tile[32][33];
    int b = blockIdx.z, c0 = blockIdx.y * 32, n0 = blockIdx.x * 32;
    int tx = threadIdx.x, ty = threadIdx.y;
    int t = ty * 16 + tx;
    const float* src = in + (size_t)b * CC * NP;
#pragma unroll
    for (int i = 0; i < 4; i++) {
        int l = t + i * 256;
        int r = l >> 5, col = l & 31;
        tile[r][col] = src[(size_t)(c0 + r) * NP + n0 + col];
    }
    __syncthreads();
#pragma unroll
    for (int yy = 0; yy < 2; yy++) {
        int nn = ty + yy * 16;
        float v0 = tile[2*tx][nn], v1 = tile[2*tx + 1][nn];
        unsigned h, l;
        packsplit(v0, v1, h, l);
        size_t o = ((size_t)b * NP + n0 + nn) * CC + c0 + 2*tx;
        *(unsigned*)(oh + o) = h;
        *(unsigned*)(ol + o) = l;
    }
}
__global__ void k_xT(const float* __restrict__ x) { tsplit_body(x, g_xTh, g_xTl); }
__global__ void k_vT()                            { tsplit_body(g_v, g_vTh, g_vTl); }

// ================= K1: conv1x1 q/k/v via HMMA bf16x3, 512 threads =================
__global__ void __launch_bounds__(512, 1) k_conv_mma(
    const float* __restrict__ qb, const float* __restrict__ kb,
    const float* __restrict__ vb)
{
    extern __shared__ __align__(16) char smem[];
    __nv_bfloat16* Bh = (__nv_bfloat16*)(smem);
    __nv_bfloat16* Bl = (__nv_bfloat16*)(smem + TILE_B);
    __nv_bfloat16* Ah = (__nv_bfloat16*)(smem + 2*TILE_B);
    __nv_bfloat16* Al = (__nv_bfloat16*)(smem + 3*TILE_B);

    int n0 = blockIdx.x * 128, b = blockIdx.y;
    size_t xoff = ((size_t)b * NP + n0) * CC;
    fill_tile512(g_xTh + xoff, CC, Bh);
    fill_tile512(g_xTl + xoff, CC, Bl);

    uint32_t uAh = smem_u32(Ah), uAl = smem_u32(Al);
    uint32_t uBh = smem_u32(Bh), uBl = smem_u32(Bl);

    int w = threadIdx.x >> 5, lane = threadIdx.x & 31;
    int wm = w & 3, wn = w >> 2;
    int er0 = wm * 32 + (lane >> 2);
    int ec0 = n0 + wn * 32 + (lane & 3) * 2;

    for (int j = 0; j < 3; j++) {
        const float* bi = (j == 0) ? qb : (j == 1) ? kb : vb;
        __syncthreads();
        fill_tile512(g_wh + (size_t)j * CC * CC, CC, Ah);
        fill_tile512(g_wl + (size_t)j * CC * CC, CC, Al);
        __syncthreads();

        float acc[2][4][4];
#pragma unroll
        for (int i = 0; i < 2; i++)
#pragma unroll
            for (int jj = 0; jj < 4; jj++)
#pragma unroll
                for (int r = 0; r < 4; r++) acc[i][jj][r] = 0.0f;

        mma_compute16(uAh, uAl, uBh, uBl, acc);

        float* O = g_t + ((size_t)j * BB + b) * CC * NP;
#pragma unroll
        for (int mt = 0; mt < 2; mt++) {
            int r = er0 + mt * 16;
            float b0 = bi[r], b1 = bi[r + 8];
#pragma unroll
            for (int nt = 0; nt < 4; nt++) {
                int c = ec0 + nt * 8;
                *(float2*)(O + (size_t)r * NP + c) =
                    make_float2(acc[mt][nt][0] + b0, acc[mt][nt][1] + b0);
                *(float2*)(O + (size_t)(r + 8) * NP + c) =
                    make_float2(acc[mt][nt][2] + b1, acc[mt][nt][3] + b1);
            }
        }
    }
}

// ================= K2: depthwise 3x3, vectorized =================
__global__ void __launch_bounds__(256) k_dwconv(
    const float* __restrict__ qdw, const float* __restrict__ qdb,
    const float* __restrict__ kdw, const float* __restrict__ kdb,
    const float* __restrict__ vdw, const float* __restrict__ vdb)
{
    int zz = blockIdx.z;
    int j = zz / BB, b = zz % BB;
    int c = blockIdx.y;
    int strip = blockIdx.x;
    const float* wsrc = ((j == 0) ? qdw : (j == 1) ? kdw : vdw) + c * 9;
    float bias = ((j == 0) ? qdb : (j == 1) ? kdb : vdb)[c];
    const float* in = g_t + (((size_t)j * BB + b) * CC + c) * NP;
    size_t obase = ((size_t)b * CC + c) * NP;

    __shared__ float s[18][136];
    float w9[9];
#pragma unroll
    for (int i = 0; i < 9; i++) w9[i] = wsrc[i];

    const int r0 = strip * 16;
    const int tid = threadIdx.x;

    if (tid < 18) { s[tid][3] = 0.0f; s[tid][132] = 0.0f; }
#pragma unroll
    for (int i = 0; i < 3; i++) {
        int idx = tid + i * 256;
        if (idx < 576) {
            int r = idx >> 5, q = idx & 31;
            int gy = r0 + r - 1;
            float4 v = make_float4(0.f, 0.f, 0.f, 0.f);
            if (gy >= 0 && gy < HH) v = *(const float4*)(in + (size_t)gy * WW + q * 4);
            *(float4*)&s[r][4 + q * 4] = v;
        }
    }
    __syncthreads();

    int r  = tid >> 4;
    int cg = (tid & 15) * 8;

    float row[3][10];
#pragma unroll
    for (int dr = 0; dr < 3; dr++) {
        const float* sp = &s[r + dr][0];
        row[dr][0] = sp[3 + cg];
        *(float4*)&row[dr][1] = *(const float4*)&sp[4 + cg];
        *(float4*)&row[dr][5] = *(const float4*)&sp[8 + cg];
        row[dr][9] = sp[12 + cg];
    }

    float out[8];
    float ssq = 0.0f;
#pragma unroll
    for (int p = 0; p < 8; p++) {
        float a = bias;
#pragma unroll
        for (int dr = 0; dr < 3; dr++)
#pragma unroll
            for (int dx = 0; dx < 3; dx++)
                a += w9[dr * 3 + dx] * row[dr][p + dx];
        out[p] = a;
        ssq += a * a;
    }

    size_t oi = obase + (size_t)(r0 + r) * WW + cg;
    if (j == 2) {
        *(float4*)(g_v + oi)     = make_float4(out[0], out[1], out[2], out[3]);
        *(float4*)(g_v + oi + 4) = make_float4(out[4], out[5], out[6], out[7]);
    } else {
        uint4 hi, lo;
        packsplit(out[0], out[1], hi.x, lo.x);
        packsplit(out[2], out[3], hi.y, lo.y);
        packsplit(out[4], out[5], hi.z, lo.z);
        packsplit(out[6], out[7], hi.w, lo.w);
        if (j == 0) { *(uint4*)(g_qh + oi) = hi; *(uint4*)(g_ql + oi) = lo; }
        else        { *(uint4*)(g_kh + oi) = hi; *(uint4*)(g_kl + oi) = lo; }
#pragma unroll
        for (int o = 16; o; o >>= 1) ssq += __shfl_down_sync(0xffffffffu, ssq, o);
        if ((tid & 31) == 0) atomicAdd(&g_ss[j * BB * CC + b * CC + c], ssq);
    }
}

// ================= K3: gram via HMMA bf16x3, 512 threads =================
__global__ void __launch_bounds__(512, 1) k_gram_mma()
{
    extern __shared__ __align__(16) char smem[];
    __nv_bfloat16* Ah = (__nv_bfloat16*)(smem);
    __nv_bfloat16* Al = (__nv_bfloat16*)(smem + TILE_B);
    __nv_bfloat16* Bh = (__nv_bfloat16*)(smem + 2*TILE_B);
    __nv_bfloat16* Bl = (__nv_bfloat16*)(smem + 3*TILE_B);

    int b = blockIdx.y;
    size_t nb = (size_t)blockIdx.x * 512;
    uint32_t uAh = smem_u32(Ah), uAl = smem_u32(Al);
    uint32_t uBh = smem_u32(Bh), uBl = smem_u32(Bl);

    float acc[2][4][4];
#pragma unroll
    for (int i = 0; i < 2; i++)
#pragma unroll
        for (int jj = 0; jj < 4; jj++)
#pragma unroll
            for (int r = 0; r < 4; r++) acc[i][jj][r] = 0.0f;

    for (int chunk = 0; chunk < 4; chunk++) {
        size_t off = (size_t)b * CC * NP + nb + chunk * 128;
        __syncthreads();
        fill_tile512(g_qh + off, NP, Ah);
        fill_tile512(g_ql + off, NP, Al);
        fill_tile512(g_kh + off, NP, Bh);
        fill_tile512(g_kl + off, NP, Bl);
        __syncthreads();
        mma_compute16(uAh, uAl, uBh, uBl, acc);
    }

    int w = threadIdx.x >> 5, lane = threadIdx.x & 31;
    int wm = w & 3, wn = w >> 2;
    int er0 = wm * 32 + (lane >> 2);
    int ec0 = wn * 32 + (lane & 3) * 2;
    float* G = g_G + (size_t)b * CC * CC;
#pragma unroll
    for (int mt = 0; mt < 2; mt++) {
        int r = er0 + mt * 16;
#pragma unroll
        for (int nt = 0; nt < 4; nt++) {
            int c = ec0 + nt * 8;
            atomicAdd(&G[r * CC + c],           acc[mt][nt][0]);
            atomicAdd(&G[r * CC + c + 1],       acc[mt][nt][1]);
            atomicAdd(&G[(r + 8) * CC + c],     acc[mt][nt][2]);
            atomicAdd(&G[(r + 8) * CC + c + 1], acc[mt][nt][3]);
        }
    }
}

// ================= K4: fold L2 norms + row softmax =================
__global__ void __launch_bounds__(128) k_softmax()
{
    int b = blockIdx.y, i = blockIdx.x;
    int t = threadIdx.x;

    float rq = 1.0f / fmaxf(sqrtf(g_ss[b * CC + i]), 1e-12f);
    float rk = 1.0f / fmaxf(sqrtf(g_ss[BB * CC + b * CC + t]), 1e-12f);
    size_t idx = (size_t)b * CC * CC + (size_t)i * CC + t;
    float val = g_G[idx] * rq * rk;

    __shared__ float redm[4];
    __shared__ float reds[4];

    float m = val;
#pragma unroll
    for (int o = 16; o; o >>= 1) m = fmaxf(m, __shfl_xor_sync(0xffffffffu, m, o));
    if ((t & 31) == 0) redm[t >> 5] = m;
    __syncthreads();
    m = fmaxf(fmaxf(redm[0], redm[1]), fmaxf(redm[2], redm[3]));

    float e = expf(val - m);
    float ssum = e;
#pragma unroll
    for (int o = 16; o; o >>= 1) ssum += __shfl_xor_sync(0xffffffffu, ssum, o);
    if ((t & 31) == 0) reds[t >> 5] = ssum;
    __syncthreads();
    float tot = reds[0] + reds[1] + reds[2] + reds[3];

    g_A[idx] = e / tot;
}

// ================= K5: M_b = aw @ A_b (SIMT — tiny) =================
__device__ __forceinline__ void gemm128_simt(
    const float* __restrict__ Wp, const float* __restrict__ Xp, int ldx,
    float* __restrict__ Op, int ldo, const float* __restrict__ bias, int n0)
{
    __shared__ float As[8][128];
    __shared__ float Bs[8][128];
    const int tid = threadIdx.x;
    const int tx = tid & 15, ty = tid >> 4;
    const int arow = tid >> 1, ak0 = (tid & 1) * 4;
    const int brow = tid >> 5, bcol = (tid & 31) * 4;

    float acc[8][8];
#pragma unroll
    for (int i = 0; i < 8; i++)
#pragma unroll
        for (int j = 0; j < 8; j++) acc[i][j] = 0.0f;

#pragma unroll 1
    for (int k0 = 0; k0 < 128; k0 += 8) {
        float4 wa = *(const float4*)(Wp + arow * 128 + k0 + ak0);
        float4 xb = *(const float4*)(Xp + (size_t)(k0 + brow) * ldx + n0 + bcol);
        __syncthreads();
        As[ak0+0][arow] = wa.x; As[ak0+1][arow] = wa.y;
        As[ak0+2][arow] = wa.z; As[ak0+3][arow] = wa.w;
        *(float4*)(&Bs[brow][bcol]) = xb;
        __syncthreads();
#pragma unroll
        for (int kk = 0; kk < 8; kk++) {
            float4 a0 = *(const float4*)&As[kk][ty*4];
            float4 a1 = *(const float4*)&As[kk][64 + ty*4];
            float4 b0 = *(const float4*)&Bs[kk][tx*4];
            float4 b1 = *(const float4*)&Bs[kk][64 + tx*4];
            float a[8] = {a0.x,a0.y,a0.z,a0.w,a1.x,a1.y,a1.z,a1.w};
            float bb[8] = {b0.x,b0.y,b0.z,b0.w,b1.x,b1.y,b1.z,b1.w};
#pragma unroll
            for (int i = 0; i < 8; i++)
#pragma unroll
                for (int j = 0; j < 8; j++) acc[i][j] += a[i] * bb[j];
        }
    }
#pragma unroll
    for (int i = 0; i < 8; i++) {
        int r = (i < 4) ? (ty*4 + i) : (64 + ty*4 + i - 4);
        float bv = bias ? bias[r] : 0.0f;
        float4 v0 = make_float4(acc[i][0]+bv, acc[i][1]+bv, acc[i][2]+bv, acc[i][3]+bv);
        float4 v1 = make_float4(acc[i][4]+bv, acc[i][5]+bv, acc[i][6]+bv, acc[i][7]+bv);
        *(float4*)(Op + (size_t)r*ldo + n0 + tx*4)      = v0;
        *(float4*)(Op + (size_t)r*ldo + n0 + 64 + tx*4) = v1;
    }
}
__global__ void __launch_bounds__(256) k_makeM(const float* __restrict__ aw)
{
    int b = blockIdx.z;
    gemm128_simt(aw, g_A + (size_t)b * CC * CC, CC, g_M + (size_t)b * CC * CC, CC, nullptr, 0);
}

// ================= K6: out = M_b @ v_b + ab via HMMA bf16x3, 512 threads =================
__global__ void __launch_bounds__(512, 1) k_final_mma(const float* __restrict__ ab,
                                                      float* __restrict__ out)
{
    extern __shared__ __align__(16) char smem[];
    __nv_bfloat16* Bh = (__nv_bfloat16*)(smem);
    __nv_bfloat16* Bl = (__nv_bfloat16*)(smem + TILE_B);
    __nv_bfloat16* Ah = (__nv_bfloat16*)(smem + 2*TILE_B);
    __nv_bfloat16* Al = (__nv_bfloat16*)(smem + 3*TILE_B);

    int n0 = blockIdx.x * 128, b = blockIdx.y;
    size_t voff = ((size_t)b * NP + n0) * CC;
    fill_tile512(g_vTh + voff, CC, Bh);
    fill_tile512(g_vTl + voff, CC, Bl);
    fill_tile512(g_Mh + (size_t)b * CC * CC, CC, Ah);
    fill_tile512(g_Ml + (size_t)b * CC * CC, CC, Al);
    __syncthreads();

    uint32_t uAh = smem_u32(Ah), uAl = smem_u32(Al);
    uint32_t uBh = smem_u32(Bh), uBl = smem_u32(Bl);

    float acc[2][4][4];
#pragma unroll
    for (int i = 0; i < 2; i++)
#pragma unroll
        for (int jj = 0; jj < 4; jj++)
#pragma unroll
            for (int r = 0; r < 4; r++) acc[i][jj][r] = 0.0f;

    mma_compute16(uAh, uAl, uBh, uBl, acc);

    int w = threadIdx.x >> 5, lane = threadIdx.x & 31;
    int wm = w & 3, wn = w >> 2;
    int er0 = wm * 32 + (lane >> 2);
    int ec0 = n0 + wn * 32 + (lane & 3) * 2;
    float* O = out + (size_t)b * CC * NP;
#pragma unroll
    for (int mt = 0; mt < 2; mt++) {
        int r = er0 + mt * 16;
        float b0 = ab[r], b1 = ab[r + 8];
#pragma unroll
        for (int nt = 0; nt < 4; nt++) {
            int c = ec0 + nt * 8;
            *(float2*)(O + (size_t)r * NP + c) =
                make_float2(acc[mt][nt][0] + b0, acc[mt][nt][1] + b0);
            *(float2*)(O + (size_t)(r + 8) * NP + c) =
                make_float2(acc[mt][nt][2] + b1, acc[mt][nt][3] + b1);
        }
    }
}

// ---------------- launch ----------------
extern "C" void kernel_launch(void* const* d_in, const int* in_sizes, int n_in,
                              void* d_out, int out_size)
{
    const float* x   = (const float*)d_in[0];
    const float* qw  = (const float*)d_in[1];
    const float* qb  = (const float*)d_in[2];
    const float* qdw = (const float*)d_in[3];
    const float* qdb = (const float*)d_in[4];
    const float* kw  = (const float*)d_in[5];
    const float* kb  = (const float*)d_in[6];
    const float* kdw = (const float*)d_in[7];
    const float* kdb = (const float*)d_in[8];
    const float* vw  = (const float*)d_in[9];
    const float* vb  = (const float*)d_in[10];
    const float* vdw = (const float*)d_in[11];
    const float* vdb = (const float*)d_in[12];
    const float* aw  = (const float*)d_in[13];
    const float* ab  = (const float*)d_in[14];
    float* out = (float*)d_out;

    const int SMEM = 4 * TILE_B;   // 139264
    cudaFuncSetAttribute(k_conv_mma,  cudaFuncAttributeMaxDynamicSharedMemorySize, SMEM);
    cudaFuncSetAttribute(k_gram_mma,  cudaFuncAttributeMaxDynamicSharedMemorySize, SMEM);
    cudaFuncSetAttribute(k_final_mma, cudaFuncAttributeMaxDynamicSharedMemorySize, SMEM);

    k_zero<<<(BB*CC*CC + 255) / 256, 256>>>();
    k_wsplit<<<3, 256>>>(qw, kw, vw);
    k_xT<<<dim3(NP/32, CC/32, BB), dim3(16, 16)>>>(x);
    k_conv_mma<<<dim3(NP/128, BB), 512, SMEM>>>(qb, kb, vb);
    k_dwconv<<<dim3(8, CC, 3*BB), 256>>>(qdw, qdb, kdw, kdb, vdw, vdb);
    k_vT<<<dim3(NP/32, CC/32, BB), dim3(16, 16)>>>();
    k_gram_mma<<<dim3(32, BB), 512, SMEM>>>();
    k_softmax<<<dim3(CC, BB), 128>>>();
    k_makeM<<<dim3(1, 1, BB), 256>>>(aw);
    k_Msplit<<<BB, 256>>>();
    k_final_mma<<<dim3(NP/128, BB), 512, SMEM>>>(ab, out);
}

// round 14
// speedup vs baseline: 1.4810x; 1.4810x over previous
#include <cuda_runtime.h>
#include <cuda_bf16.h>
#include <math.h>
#include <stdint.h>

#define BB 16
#define CC 128
#define HH 128
#define WW 128
#define NP (HH*WW)          // 16384 spatial

#define LDT 136             // padded smem row stride (bf16) for 128-wide tiles
#define TILE_B (128*LDT*2)  // 34816 bytes per 128x128 bf16 tile
#define LDT64 72            // padded row stride for 64-wide tiles
#define TILE64 (128*LDT64*2)// 18432 bytes per 128x64 bf16 tile

// ---------------- scratch (device globals; no allocation allowed) ----------------
__device__ float g_t [3ull*BB*CC*NP];            // conv1x1 outputs fp32 (dwconv input)
__device__ float g_v [(size_t)BB*CC*NP];         // v after dwconv, fp32 [b][c][n]
__device__ __nv_bfloat16 g_xTh[(size_t)BB*NP*CC];// x transposed [b][n][c], hi
__device__ __nv_bfloat16 g_xTl[(size_t)BB*NP*CC];// lo
__device__ __nv_bfloat16 g_vTh[(size_t)BB*NP*CC];// v transposed, hi
__device__ __nv_bfloat16 g_vTl[(size_t)BB*NP*CC];
__device__ __nv_bfloat16 g_qh[(size_t)BB*CC*NP]; // q after dwconv [b][c][n], hi
__device__ __nv_bfloat16 g_ql[(size_t)BB*CC*NP];
__device__ __nv_bfloat16 g_kh[(size_t)BB*CC*NP];
__device__ __nv_bfloat16 g_kl[(size_t)BB*CC*NP];
__device__ __nv_bfloat16 g_wh[3ull*CC*CC];       // qw/kw/vw pre-split hi
__device__ __nv_bfloat16 g_wl[3ull*CC*CC];       // lo
__device__ __nv_bfloat16 g_Mh[(size_t)BB*CC*CC]; // M pre-split hi
__device__ __nv_bfloat16 g_Ml[(size_t)BB*CC*CC];
__device__ float g_ss[2*BB*CC];
__device__ float g_G [BB*CC*CC];
__device__ float g_A [BB*CC*CC];
__device__ float g_M [BB*CC*CC];

// ================= helpers =================
__device__ __forceinline__ uint32_t smem_u32(const void* p) {
    uint32_t a;
    asm("{ .reg .u64 t; cvta.to.shared.u64 t, %1; cvt.u32.u64 %0, t; }" : "=r"(a) : "l"(p));
    return a;
}
__device__ __forceinline__ void cp16(uint32_t s, const void* g) {
    asm volatile("cp.async.cg.shared.global [%0], [%1], 16;" :: "r"(s), "l"(g) : "memory");
}
#define CP_COMMIT() asm volatile("cp.async.commit_group;" ::: "memory")
#define CP_WAIT1()  asm volatile("cp.async.wait_group 1;" ::: "memory")
#define CP_WAIT0()  asm volatile("cp.async.wait_group 0;" ::: "memory")

__device__ __forceinline__ void ldmx4(uint32_t addr, uint32_t* r) {
    asm volatile("ldmatrix.sync.aligned.m8n8.x4.shared.b16 {%0,%1,%2,%3}, [%4];"
        : "=r"(r[0]), "=r"(r[1]), "=r"(r[2]), "=r"(r[3]) : "r"(addr));
}
__device__ __forceinline__ void mma16816(float* d, const uint32_t* a, const uint32_t* b) {
    asm volatile("mma.sync.aligned.m16n8k16.row.col.f32.bf16.bf16.f32 "
        "{%0,%1,%2,%3}, {%4,%5,%6,%7}, {%8,%9}, {%0,%1,%2,%3};"
        : "+f"(d[0]), "+f"(d[1]), "+f"(d[2]), "+f"(d[3])
        : "r"(a[0]), "r"(a[1]), "r"(a[2]), "r"(a[3]), "r"(b[0]), "r"(b[1]));
}
__device__ __forceinline__ void packsplit(float x, float y, unsigned& h, unsigned& l) {
    __nv_bfloat16 hx = __float2bfloat16(x), hy = __float2bfloat16(y);
    __nv_bfloat16 lx = __float2bfloat16(x - __bfloat162float(hx));
    __nv_bfloat16 ly = __float2bfloat16(y - __bfloat162float(hy));
    h = (unsigned)__bfloat16_as_ushort(hx) | ((unsigned)__bfloat16_as_ushort(hy) << 16);
    l = (unsigned)__bfloat16_as_ushort(lx) | ((unsigned)__bfloat16_as_ushort(ly) << 16);
}

// async fill of a 128x128 bf16 tile into padded smem (256 threads)
__device__ __forceinline__ void fill_async128(const __nv_bfloat16* __restrict__ src,
                                              size_t stride, uint32_t dst) {
    int t = threadIdx.x;
    int row = t >> 1, h = t & 1;
    const char* s = (const char*)(src + (size_t)row * stride) + h * 128;
    uint32_t d = dst + (uint32_t)(row * LDT + h * 64) * 2;
#pragma unroll
    for (int i = 0; i < 8; i++) cp16(d + i * 16, s + i * 16);
}
// async fill of a 128x64 bf16 tile into padded smem (256 threads)
__device__ __forceinline__ void fill_async64(const __nv_bfloat16* __restrict__ src,
                                             size_t stride, uint32_t dst) {
    int t = threadIdx.x;
    int row = t >> 1, h = t & 1;
    const char* s = (const char*)(src + (size_t)row * stride) + h * 64;
    uint32_t d = dst + (uint32_t)(row * LDT64) * 2 + h * 64;
#pragma unroll
    for (int i = 0; i < 4; i++) cp16(d + i * 16, s + i * 16);
}

// ---- 8-warp 128x128xK compensated bf16 MMA (R11 shape): acc += Ah.Bh + Al.Bh + Ah.Bl ----
template<int NKS, int LD>
__device__ __forceinline__ void mma_compute_t(uint32_t sAh, uint32_t sAl,
                                              uint32_t sBh, uint32_t sBl,
                                              float acc[4][4][4]) {
    int w = threadIdx.x >> 5, lane = threadIdx.x & 31;
    int wm = w & 1, wn = w >> 1;

    int arow = lane & 15;
    int acol = (lane >> 4) * 8;
    uint32_t aoff[4];
#pragma unroll
    for (int mt = 0; mt < 4; mt++)
        aoff[mt] = ((wm * 64 + mt * 16 + arow) * LD + acol) * 2;

    int brow = ((lane >> 4) & 1) * 8 + (lane & 7);
    int bcol = ((lane >> 3) & 1) * 8;
    uint32_t boff[2];
#pragma unroll
    for (int np = 0; np < 2; np++)
        boff[np] = ((wn * 32 + np * 16 + brow) * LD + bcol) * 2;

#pragma unroll
    for (int ks = 0; ks < NKS; ks++) {
        uint32_t kb = ks * 32;
        uint32_t ah[4][4], al[4][4], bb[2][4];
#pragma unroll
        for (int mt = 0; mt < 4; mt++) ldmx4(sAh + aoff[mt] + kb, ah[mt]);
#pragma unroll
        for (int np = 0; np < 2; np++) ldmx4(sBh + boff[np] + kb, bb[np]);
#pragma unroll
        for (int mt = 0; mt < 4; mt++)
#pragma unroll
            for (int nt = 0; nt < 4; nt++)
                mma16816(acc[mt][nt], ah[mt], &bb[nt >> 1][(nt & 1) * 2]);
#pragma unroll
        for (int mt = 0; mt < 4; mt++) ldmx4(sAl + aoff[mt] + kb, al[mt]);
#pragma unroll
        for (int mt = 0; mt < 4; mt++)
#pragma unroll
            for (int nt = 0; nt < 4; nt++)
                mma16816(acc[mt][nt], al[mt], &bb[nt >> 1][(nt & 1) * 2]);
#pragma unroll
        for (int np = 0; np < 2; np++) ldmx4(sBl + boff[np] + kb, bb[np]);
#pragma unroll
        for (int mt = 0; mt < 4; mt++)
#pragma unroll
            for (int nt = 0; nt < 4; nt++)
                mma16816(acc[mt][nt], ah[mt], &bb[nt >> 1][(nt & 1) * 2]);
    }
}

// ---------------- zero accumulators ----------------
__global__ void k_zero() {
    int i = blockIdx.x * blockDim.x + threadIdx.x;
    if (i < BB*CC*CC) g_G[i] = 0.0f;
    if (i < 2*BB*CC)  g_ss[i] = 0.0f;
}

// ---------------- pre-split weights to bf16 hi/lo ----------------
__global__ void __launch_bounds__(256) k_wsplit(const float* __restrict__ qw,
                                                const float* __restrict__ kw,
                                                const float* __restrict__ vw)
{
    int j = blockIdx.x;
    const float* W = (j == 0) ? qw : (j == 1) ? kw : vw;
    __nv_bfloat16* oh = g_wh + (size_t)j * CC * CC;
    __nv_bfloat16* ol = g_wl + (size_t)j * CC * CC;
    int t = threadIdx.x;
#pragma unroll
    for (int i = 0; i < 16; i++) {
        int l = t + i * 256;
        float4 a = ((const float4*)W)[l];
        unsigned h0, l0, h1, l1;
        packsplit(a.x, a.y, h0, l0);
        packsplit(a.z, a.w, h1, l1);
        ((uint2*)oh)[l] = make_uint2(h0, h1);
        ((uint2*)ol)[l] = make_uint2(l0, l1);
    }
}
__global__ void __launch_bounds__(256) k_Msplit()
{
    int b = blockIdx.x;
    const float* W = g_M + (size_t)b * CC * CC;
    __nv_bfloat16* oh = g_Mh + (size_t)b * CC * CC;
    __nv_bfloat16* ol = g_Ml + (size_t)b * CC * CC;
    int t = threadIdx.x;
#pragma unroll
    for (int i = 0; i < 16; i++) {
        int l = t + i * 256;
        float4 a = ((const float4*)W)[l];
        unsigned h0, l0, h1, l1;
        packsplit(a.x, a.y, h0, l0);
        packsplit(a.z, a.w, h1, l1);
        ((uint2*)oh)[l] = make_uint2(h0, h1);
        ((uint2*)ol)[l] = make_uint2(l0, l1);
    }
}

// ---------------- transpose + bf16 split ----------------
__device__ __forceinline__ void tsplit_body(const float* __restrict__ in,
                                            __nv_bfloat16* __restrict__ oh,
                                            __nv_bfloat16* __restrict__ ol) {
    __shared__ float tile[32][33];
    int b = blockIdx.z, c0 = blockIdx.y * 32, n0 = blockIdx.x * 32;
    int tx = threadIdx.x, ty = threadIdx.y;
    int t = ty * 16 + tx;
    const float* src = in + (size_t)b * CC * NP;
#pragma unroll
    for (int i = 0; i < 4; i++) {
        int l = t + i * 256;
        int r = l >> 5, col = l & 31;
        tile[r][col] = src[(size_t)(c0 + r) * NP + n0 + col];
    }
    __syncthreads();
#pragma unroll
    for (int yy = 0; yy < 2; yy++) {
        int nn = ty + yy * 16;
        float v0 = tile[2*tx][nn], v1 = tile[2*tx + 1][nn];
        unsigned h, l;
        packsplit(v0, v1, h, l);
        size_t o = ((size_t)b * NP + n0 + nn) * CC + c0 + 2*tx;
        *(unsigned*)(oh + o) = h;
        *(unsigned*)(ol + o) = l;
    }
}
__global__ void k_xT(const float* __restrict__ x) { tsplit_body(x, g_xTh, g_xTl); }
__global__ void k_vT()                            { tsplit_body(g_v, g_vTh, g_vTl); }

// ================= K1: conv1x1 q/k/v via HMMA bf16x3, cp.async A double-buffer =================
// smem: Bh@0, Bl@T, A0(h,l)@2T..4T, A1(h,l)@4T..6T  = 6T = 208896
#define CONV_SMEM (6*TILE_B)
__global__ void __launch_bounds__(256, 1) k_conv_mma(
    const float* __restrict__ qb, const float* __restrict__ kb,
    const float* __restrict__ vb)
{
    extern __shared__ __align__(16) char smem[];
    uint32_t sb  = smem_u32(smem);
    uint32_t uBh = sb, uBl = sb + TILE_B;
    uint32_t uA[2] = { sb + 2*TILE_B, sb + 4*TILE_B };   // each: Ah @+0, Al @+TILE_B

    int n0 = blockIdx.x * 128, b = blockIdx.y;
    size_t xoff = ((size_t)b * NP + n0) * CC;
    fill_async128(g_xTh + xoff, CC, uBh);
    fill_async128(g_xTl + xoff, CC, uBl);
    fill_async128(g_wh, CC, uA[0]);
    fill_async128(g_wl, CC, uA[0] + TILE_B);
    CP_COMMIT();

    int w = threadIdx.x >> 5, lane = threadIdx.x & 31;
    int wm = w & 1, wn = w >> 1;
    int er0 = wm * 64 + (lane >> 2);
    int ec0 = n0 + wn * 32 + (lane & 3) * 2;

    for (int j = 0; j < 3; j++) {
        const float* bi = (j == 0) ? qb : (j == 1) ? kb : vb;
        __syncthreads();                  // target buffer no longer in use
        if (j < 2) {
            fill_async128(g_wh + (size_t)(j+1) * CC * CC, CC, uA[(j+1) & 1]);
            fill_async128(g_wl + (size_t)(j+1) * CC * CC, CC, uA[(j+1) & 1] + TILE_B);
            CP_COMMIT();
            CP_WAIT1();                   // wait for current j's data (overlap j+1 copy)
        } else {
            CP_WAIT0();
        }
        __syncthreads();

        float acc[4][4][4];
#pragma unroll
        for (int i = 0; i < 4; i++)
#pragma unroll
            for (int jj = 0; jj < 4; jj++)
#pragma unroll
                for (int r = 0; r < 4; r++) acc[i][jj][r] = 0.0f;

        mma_compute_t<8, LDT>(uA[j & 1], uA[j & 1] + TILE_B, uBh, uBl, acc);

        float* O = g_t + ((size_t)j * BB + b) * CC * NP;
#pragma unroll
        for (int mt = 0; mt < 4; mt++) {
            int r = er0 + mt * 16;
            float b0 = bi[r], b1 = bi[r + 8];
#pragma unroll
            for (int nt = 0; nt < 4; nt++) {
                int c = ec0 + nt * 8;
                *(float2*)(O + (size_t)r * NP + c) =
                    make_float2(acc[mt][nt][0] + b0, acc[mt][nt][1] + b0);
                *(float2*)(O + (size_t)(r + 8) * NP + c) =
                    make_float2(acc[mt][nt][2] + b1, acc[mt][nt][3] + b1);
            }
        }
    }
}

// ================= K2: depthwise 3x3, vectorized =================
__global__ void __launch_bounds__(256) k_dwconv(
    const float* __restrict__ qdw, const float* __restrict__ qdb,
    const float* __restrict__ kdw, const float* __restrict__ kdb,
    const float* __restrict__ vdw, const float* __restrict__ vdb)
{
    int zz = blockIdx.z;
    int j = zz / BB, b = zz % BB;
    int c = blockIdx.y;
    int strip = blockIdx.x;
    const float* wsrc = ((j == 0) ? qdw : (j == 1) ? kdw : vdw) + c * 9;
    float bias = ((j == 0) ? qdb : (j == 1) ? kdb : vdb)[c];
    const float* in = g_t + (((size_t)j * BB + b) * CC + c) * NP;
    size_t obase = ((size_t)b * CC + c) * NP;

    __shared__ float s[18][136];
    float w9[9];
#pragma unroll
    for (int i = 0; i < 9; i++) w9[i] = wsrc[i];

    const int r0 = strip * 16;
    const int tid = threadIdx.x;

    if (tid < 18) { s[tid][3] = 0.0f; s[tid][132] = 0.0f; }
#pragma unroll
    for (int i = 0; i < 3; i++) {
        int idx = tid + i * 256;
        if (idx < 576) {
            int r = idx >> 5, q = idx & 31;
            int gy = r0 + r - 1;
            float4 v = make_float4(0.f, 0.f, 0.f, 0.f);
            if (gy >= 0 && gy < HH) v = *(const float4*)(in + (size_t)gy * WW + q * 4);
            *(float4*)&s[r][4 + q * 4] = v;
        }
    }
    __syncthreads();

    int r  = tid >> 4;
    int cg = (tid & 15) * 8;

    float row[3][10];
#pragma unroll
    for (int dr = 0; dr < 3; dr++) {
        const float* sp = &s[r + dr][0];
        row[dr][0] = sp[3 + cg];
        *(float4*)&row[dr][1] = *(const float4*)&sp[4 + cg];
        *(float4*)&row[dr][5] = *(const float4*)&sp[8 + cg];
        row[dr][9] = sp[12 + cg];
    }

    float out[8];
    float ssq = 0.0f;
#pragma unroll
    for (int p = 0; p < 8; p++) {
        float a = bias;
#pragma unroll
        for (int dr = 0; dr < 3; dr++)
#pragma unroll
            for (int dx = 0; dx < 3; dx++)
                a += w9[dr * 3 + dx] * row[dr][p + dx];
        out[p] = a;
        ssq += a * a;
    }

    size_t oi = obase + (size_t)(r0 + r) * WW + cg;
    if (j == 2) {
        *(float4*)(g_v + oi)     = make_float4(out[0], out[1], out[2], out[3]);
        *(float4*)(g_v + oi + 4) = make_float4(out[4], out[5], out[6], out[7]);
    } else {
        uint4 hi, lo;
        packsplit(out[0], out[1], hi.x, lo.x);
        packsplit(out[2], out[3], hi.y, lo.y);
        packsplit(out[4], out[5], hi.z, lo.z);
        packsplit(out[6], out[7], hi.w, lo.w);
        if (j == 0) { *(uint4*)(g_qh + oi) = hi; *(uint4*)(g_ql + oi) = lo; }
        else        { *(uint4*)(g_kh + oi) = hi; *(uint4*)(g_kl + oi) = lo; }
#pragma unroll
        for (int o = 16; o; o >>= 1) ssq += __shfl_down_sync(0xffffffffu, ssq, o);
        if ((tid & 31) == 0) atomicAdd(&g_ss[j * BB * CC + b * CC + c], ssq);
    }
}

// ================= K3: gram via HMMA bf16x3, 64-col chunks, cp.async double-buffer =================
// smem: 2 bufs x (qh,ql,kh,kl) x TILE64 = 147456
#define GRAM_SMEM (8*TILE64)
__global__ void __launch_bounds__(256, 1) k_gram_mma()
{
    extern __shared__ __align__(16) char smem[];
    uint32_t sb = smem_u32(smem);

    int b = blockIdx.y;
    size_t nb = (size_t)blockIdx.x * 512;
    size_t base = (size_t)b * CC * NP;

    float acc[4][4][4];
#pragma unroll
    for (int i = 0; i < 4; i++)
#pragma unroll
        for (int jj = 0; jj < 4; jj++)
#pragma unroll
            for (int r = 0; r < 4; r++) acc[i][jj][r] = 0.0f;

    auto fill = [&](int buf, int chunk) {
        size_t off = base + nb + (size_t)chunk * 64;
        uint32_t d = sb + buf * (4 * TILE64);
        fill_async64(g_qh + off, NP, d);
        fill_async64(g_ql + off, NP, d + TILE64);
        fill_async64(g_kh + off, NP, d + 2 * TILE64);
        fill_async64(g_kl + off, NP, d + 3 * TILE64);
    };

    fill(0, 0);
    CP_COMMIT();

    for (int c = 0; c < 8; c++) {
        __syncthreads();                  // next fill target buffer free
        if (c < 7) {
            fill((c + 1) & 1, c + 1);
            CP_COMMIT();
            CP_WAIT1();
        } else {
            CP_WAIT0();
        }
        __syncthreads();
        uint32_t d = sb + (c & 1) * (4 * TILE64);
        mma_compute_t<4, LDT64>(d, d + TILE64, d + 2 * TILE64, d + 3 * TILE64, acc);
    }

    int w = threadIdx.x >> 5, lane = threadIdx.x & 31;
    int wm = w & 1, wn = w >> 1;
    int er0 = wm * 64 + (lane >> 2);
    int ec0 = wn * 32 + (lane & 3) * 2;
    float* G = g_G + (size_t)b * CC * CC;
#pragma unroll
    for (int mt = 0; mt < 4; mt++) {
        int r = er0 + mt * 16;
#pragma unroll
        for (int nt = 0; nt < 4; nt++) {
            int c = ec0 + nt * 8;
            atomicAdd(&G[r * CC + c],           acc[mt][nt][0]);
            atomicAdd(&G[r * CC + c + 1],       acc[mt][nt][1]);
            atomicAdd(&G[(r + 8) * CC + c],     acc[mt][nt][2]);
            atomicAdd(&G[(r + 8) * CC + c + 1], acc[mt][nt][3]);
        }
    }
}

// ================= K4: fold L2 norms + row softmax =================
__global__ void __launch_bounds__(128) k_softmax()
{
    int b = blockIdx.y, i = blockIdx.x;
    int t = threadIdx.x;

    float rq = 1.0f / fmaxf(sqrtf(g_ss[b * CC + i]), 1e-12f);
    float rk = 1.0f / fmaxf(sqrtf(g_ss[BB * CC + b * CC + t]), 1e-12f);
    size_t idx = (size_t)b * CC * CC + (size_t)i * CC + t;
    float val = g_G[idx] * rq * rk;

    __shared__ float redm[4];
    __shared__ float reds[4];

    float m = val;
#pragma unroll
    for (int o = 16; o; o >>= 1) m = fmaxf(m, __shfl_xor_sync(0xffffffffu, m, o));
    if ((t & 31) == 0) redm[t >> 5] = m;
    __syncthreads();
    m = fmaxf(fmaxf(redm[0], redm[1]), fmaxf(redm[2], redm[3]));

    float e = expf(val - m);
    float ssum = e;
#pragma unroll
    for (int o = 16; o; o >>= 1) ssum += __shfl_xor_sync(0xffffffffu, ssum, o);
    if ((t & 31) == 0) reds[t >> 5] = ssum;
    __syncthreads();
    float tot = reds[0] + reds[1] + reds[2] + reds[3];

    g_A[idx] = e / tot;
}

// ================= K5: M_b = aw @ A_b (SIMT — tiny) =================
__device__ __forceinline__ void gemm128_simt(
    const float* __restrict__ Wp, const float* __restrict__ Xp, int ldx,
    float* __restrict__ Op, int ldo, const float* __restrict__ bias, int n0)
{
    __shared__ float As[8][128];
    __shared__ float Bs[8][128];
    const int tid = threadIdx.x;
    const int tx = tid & 15, ty = tid >> 4;
    const int arow = tid >> 1, ak0 = (tid & 1) * 4;
    const int brow = tid >> 5, bcol = (tid & 31) * 4;

    float acc[8][8];
#pragma unroll
    for (int i = 0; i < 8; i++)
#pragma unroll
        for (int j = 0; j < 8; j++) acc[i][j] = 0.0f;

#pragma unroll 1
    for (int k0 = 0; k0 < 128; k0 += 8) {
        float4 wa = *(const float4*)(Wp + arow * 128 + k0 + ak0);
        float4 xb = *(const float4*)(Xp + (size_t)(k0 + brow) * ldx + n0 + bcol);
        __syncthreads();
        As[ak0+0][arow] = wa.x; As[ak0+1][arow] = wa.y;
        As[ak0+2][arow] = wa.z; As[ak0+3][arow] = wa.w;
        *(float4*)(&Bs[brow][bcol]) = xb;
        __syncthreads();
#pragma unroll
        for (int kk = 0; kk < 8; kk++) {
            float4 a0 = *(const float4*)&As[kk][ty*4];
            float4 a1 = *(const float4*)&As[kk][64 + ty*4];
            float4 b0 = *(const float4*)&Bs[kk][tx*4];
            float4 b1 = *(const float4*)&Bs[kk][64 + tx*4];
            float a[8] = {a0.x,a0.y,a0.z,a0.w,a1.x,a1.y,a1.z,a1.w};
            float bb[8] = {b0.x,b0.y,b0.z,b0.w,b1.x,b1.y,b1.z,b1.w};
#pragma unroll
            for (int i = 0; i < 8; i++)
#pragma unroll
                for (int j = 0; j < 8; j++) acc[i][j] += a[i] * bb[j];
        }
    }
#pragma unroll
    for (int i = 0; i < 8; i++) {
        int r = (i < 4) ? (ty*4 + i) : (64 + ty*4 + i - 4);
        float bv = bias ? bias[r] : 0.0f;
        float4 v0 = make_float4(acc[i][0]+bv, acc[i][1]+bv, acc[i][2]+bv, acc[i][3]+bv);
        float4 v1 = make_float4(acc[i][4]+bv, acc[i][5]+bv, acc[i][6]+bv, acc[i][7]+bv);
        *(float4*)(Op + (size_t)r*ldo + n0 + tx*4)      = v0;
        *(float4*)(Op + (size_t)r*ldo + n0 + 64 + tx*4) = v1;
    }
}
__global__ void __launch_bounds__(256) k_makeM(const float* __restrict__ aw)
{
    int b = blockIdx.z;
    gemm128_simt(aw, g_A + (size_t)b * CC * CC, CC, g_M + (size_t)b * CC * CC, CC, nullptr, 0);
}

// ================= K6: out = M_b @ v_b + ab via HMMA bf16x3, cp.async fills =================
#define FINAL_SMEM (4*TILE_B)
__global__ void __launch_bounds__(256, 1) k_final_mma(const float* __restrict__ ab,
                                                      float* __restrict__ out)
{
    extern __shared__ __align__(16) char smem[];
    uint32_t sb  = smem_u32(smem);
    uint32_t uBh = sb, uBl = sb + TILE_B;
    uint32_t uAh = sb + 2*TILE_B, uAl = sb + 3*TILE_B;

    int n0 = blockIdx.x * 128, b = blockIdx.y;
    size_t voff = ((size_t)b * NP + n0) * CC;
    fill_async128(g_vTh + voff, CC, uBh);
    fill_async128(g_vTl + voff, CC, uBl);
    fill_async128(g_Mh + (size_t)b * CC * CC, CC, uAh);
    fill_async128(g_Ml + (size_t)b * CC * CC, CC, uAl);
    CP_COMMIT();
    CP_WAIT0();
    __syncthreads();

    float acc[4][4][4];
#pragma unroll
    for (int i = 0; i < 4; i++)
#pragma unroll
        for (int jj = 0; jj < 4; jj++)
#pragma unroll
            for (int r = 0; r < 4; r++) acc[i][jj][r] = 0.0f;

    mma_compute_t<8, LDT>(uAh, uAl, uBh, uBl, acc);

    int w = threadIdx.x >> 5, lane = threadIdx.x & 31;
    int wm = w & 1, wn = w >> 1;
    int er0 = wm * 64 + (lane >> 2);
    int ec0 = n0 + wn * 32 + (lane & 3) * 2;
    float* O = out + (size_t)b * CC * NP;
#pragma unroll
    for (int mt = 0; mt < 4; mt++) {
        int r = er0 + mt * 16;
        float b0 = ab[r], b1 = ab[r + 8];
#pragma unroll
        for (int nt = 0; nt < 4; nt++) {
            int c = ec0 + nt * 8;
            *(float2*)(O + (size_t)r * NP + c) =
                make_float2(acc[mt][nt][0] + b0, acc[mt][nt][1] + b0);
            *(float2*)(O + (size_t)(r + 8) * NP + c) =
                make_float2(acc[mt][nt][2] + b1, acc[mt][nt][3] + b1);
        }
    }
}

// ---------------- launch ----------------
extern "C" void kernel_launch(void* const* d_in, const int* in_sizes, int n_in,
                              void* d_out, int out_size)
{
    const float* x   = (const float*)d_in[0];
    const float* qw  = (const float*)d_in[1];
    const float* qb  = (const float*)d_in[2];
    const float* qdw = (const float*)d_in[3];
    const float* qdb = (const float*)d_in[4];
    const float* kw  = (const float*)d_in[5];
    const float* kb  = (const float*)d_in[6];
    const float* kdw = (const float*)d_in[7];
    const float* kdb = (const float*)d_in[8];
    const float* vw  = (const float*)d_in[9];
    const float* vb  = (const float*)d_in[10];
    const float* vdw = (const float*)d_in[11];
    const float* vdb = (const float*)d_in[12];
    const float* aw  = (const float*)d_in[13];
    const float* ab  = (const float*)d_in[14];
    float* out = (float*)d_out;

    cudaFuncSetAttribute(k_conv_mma,  cudaFuncAttributeMaxDynamicSharedMemorySize, CONV_SMEM);
    cudaFuncSetAttribute(k_gram_mma,  cudaFuncAttributeMaxDynamicSharedMemorySize, GRAM_SMEM);
    cudaFuncSetAttribute(k_final_mma, cudaFuncAttributeMaxDynamicSharedMemorySize, FINAL_SMEM);

    k_zero<<<(BB*CC*CC + 255) / 256, 256>>>();
    k_wsplit<<<3, 256>>>(qw, kw, vw);
    k_xT<<<dim3(NP/32, CC/32, BB), dim3(16, 16)>>>(x);
    k_conv_mma<<<dim3(NP/128, BB), 256, CONV_SMEM>>>(qb, kb, vb);
    k_dwconv<<<dim3(8, CC, 3*BB), 256>>>(qdw, qdb, kdw, kdb, vdw, vdb);
    k_vT<<<dim3(NP/32, CC/32, BB), dim3(16, 16)>>>();
    k_gram_mma<<<dim3(32, BB), 256, GRAM_SMEM>>>();
    k_softmax<<<dim3(CC, BB), 128>>>();
    k_makeM<<<dim3(1, 1, BB), 256>>>(aw);
    k_Msplit<<<BB, 256>>>();
    k_final_mma<<<dim3(NP/128, BB), 256, FINAL_SMEM>>>(ab, out);
}